// round 6
// baseline (speedup 1.0000x reference)
#include <cuda_runtime.h>
#include <cstdint>
#include <float.h>

#define BB 8
#define NN 2048
#define CC 128
#define KK 9
#define CO 256
#define NROWS (BB*NN)        // 16384

// ---- scratch (device globals: allocation-free contract) ----
__device__ float g_sq[NROWS];
__device__ int   g_nn[NROWS*KK];
__device__ float g_M2T[CC*512];
__device__ float g_PQ[(size_t)NROWS*512];
__device__ float g_Hsel[(size_t)NROWS*CO];
__device__ float g_part[512*512];
__device__ float g_scale[CO];
__device__ float g_shift[CO];
__device__ float g_XTh[(size_t)NROWS*CC];   // x transposed [b][n][c], tf32 hi part
__device__ float g_XTl[(size_t)NROWS*CC];   // tf32 residual

__device__ __forceinline__ float tf32r(float x) {
    uint32_t r;
    asm("cvt.rna.tf32.f32 %0, %1;" : "=r"(r) : "f"(x));
    return __uint_as_float(r);
}
__device__ __forceinline__ uint32_t smem_u32(const void* p) {
    uint32_t a;
    asm("{ .reg .u64 t; cvta.to.shared.u64 t, %1; cvt.u32.u64 %0, t; }" : "=r"(a) : "l"(p));
    return a;
}

// warp-level tf32 MMA (sm_80+ generic PTX)
#define MMA_TF32(c0,c1,c2,c3, a0,a1,a2,a3, b0,b1)                          \
    asm volatile("mma.sync.aligned.m16n8k8.row.col.f32.tf32.tf32.f32 "     \
        "{%0,%1,%2,%3}, {%4,%5,%6,%7}, {%8,%9}, {%0,%1,%2,%3};"            \
        : "+f"(c0), "+f"(c1), "+f"(c2), "+f"(c3)                           \
        : "r"(a0), "r"(a1), "r"(a2), "r"(a3), "r"(b0), "r"(b1))

#define LDSM_X4(r0,r1,r2,r3, addr)                                          \
    asm volatile("ldmatrix.sync.aligned.m8n8.x4.shared.b16 {%0,%1,%2,%3}, [%4];" \
        : "=r"(r0), "=r"(r1), "=r"(r2), "=r"(r3) : "r"(addr))

// ------------------------------------------------------------------
// prep: M2T = [[W1-W2];[W2]] transposed to [c][o']
// ------------------------------------------------------------------
__global__ void prep_k(const float* __restrict__ W) {
    int i = blockIdx.x*256 + threadIdx.x;
    if (i >= 512*CC) return;
    int c = i >> 9, o = i & 511;
    float v;
    if (o < CO) v = W[o*256 + c] - W[o*256 + 128 + c];
    else        v = W[(o-CO)*256 + 128 + c];
    g_M2T[c*512 + o] = v;
}

// ------------------------------------------------------------------
// sq: per-point squared norm (x layout [b][c][n])
// ------------------------------------------------------------------
__global__ void sq_k(const float* __restrict__ x) {
    int t = blockIdx.x*256 + threadIdx.x;
    int b = t >> 11, n = t & (NN-1);
    const float* xb = x + (size_t)b*CC*NN + n;
    float s = 0.f;
    #pragma unroll 8
    for (int c = 0; c < CC; c++) { float v = xb[(size_t)c*NN]; s = fmaf(v, v, s); }
    g_sq[t] = s;
}

// ------------------------------------------------------------------
// xt: transpose x [b][c][n] -> XTh/XTl [b][n][c] with tf32 hi/lo split
// ------------------------------------------------------------------
__global__ void xt_k(const float* __restrict__ x) {
    __shared__ float t[32][33];
    int b = blockIdx.z, n0 = blockIdx.x*32, c0 = blockIdx.y*32;
    int tx = threadIdx.x, ty = threadIdx.y;   // 32 x 8
    #pragma unroll
    for (int i = 0; i < 4; i++)
        t[ty + i*8][tx] = x[((size_t)(b*CC + c0 + ty + i*8))*NN + n0 + tx];
    __syncthreads();
    #pragma unroll
    for (int i = 0; i < 4; i++) {
        int n = n0 + ty + i*8;
        float v = t[tx][ty + i*8];
        float hi = tf32r(v);
        float lo = tf32r(v - hi);
        size_t idx = ((size_t)(b*NN + n))*CC + c0 + tx;
        g_XTh[idx] = hi;
        g_XTl[idx] = lo;
    }
}

// ------------------------------------------------------------------
// gram_mma v2: tf32 mma.sync 3-pass Gram + fused per-row top-9.
// 512 threads = 16 warps in 8m x 2n; warp tile 16x32 over 128x64 tiles.
// ldmatrix fragment loads; XOR-swizzled smem rows (128 floats/row).
// Per thread: acc 16 regs, top-9 state for 2 rows (36 regs).
// smem: Ah | Al (128x128 each) | Bh | Bl (64x128 each) = 192KB.
// ------------------------------------------------------------------
__global__ __launch_bounds__(512, 1) void gram_mma_k() {
    extern __shared__ float sm[];
    float* sAh = sm;               // 128*128
    float* sAl = sm + 16384;       // 128*128
    float* sBh = sm + 32768;       // 64*128
    float* sBl = sm + 40960;       // 64*128
    __shared__ float sSq[64];

    const int tid  = threadIdx.x;
    const int warp = tid >> 5, lane = tid & 31;
    const int qr = lane >> 2, qc = lane & 3;
    const int wm = (warp >> 1) * 16;   // row base (8 m-groups)
    const int wn = (warp & 1) * 32;    // col base (2 n-groups)
    const int b = blockIdx.y, n0 = blockIdx.x*128;

    const uint32_t sAh_u = smem_u32(sAh), sAl_u = smem_u32(sAl);
    const uint32_t sBh_u = smem_u32(sBh), sBl_u = smem_u32(sBl);

    // ldmatrix per-lane source rows (swizzle applied per-ks below)
    const int arow = wm + (lane & 7) + ((lane >> 3) & 1) * 8;
    const int ach  = (lane >> 4) & 1;                 // k half (0: k0, 1: k0+4)
    const int brow_lo = wn + (lane & 7) + ((lane >> 4) << 3);  // rows for B pair 0
    const int bch  = (lane >> 3) & 1;

    // load A strip: 128 rows x 32 float4, swizzled: c4 ^ (row & 7)
    {
        const float4* srcH = (const float4*)(g_XTh + (size_t)(b*NN + n0)*CC);
        const float4* srcL = (const float4*)(g_XTl + (size_t)(b*NN + n0)*CC);
        #pragma unroll
        for (int it = 0; it < 8; it++) {
            int g = it*512 + tid;
            int row = g >> 5, c4 = g & 31;
            int o = row*128 + ((c4 ^ (row & 7)) << 2);
            *(float4*)&sAh[o] = srcH[g];
            *(float4*)&sAl[o] = srcL[g];
        }
    }

    float tv[2][9]; int ti[2][9];
    #pragma unroll
    for (int r = 0; r < 2; r++)
        #pragma unroll
        for (int q = 0; q < KK; q++) { tv[r][q] = FLT_MAX; ti[r][q] = 0x7FFFFFFF; }

    for (int mt = 0; mt < NN/64; mt++) {
        const int m0 = mt*64;
        __syncthreads();
        {
            const float4* srcH = (const float4*)(g_XTh + (size_t)(b*NN + m0)*CC);
            const float4* srcL = (const float4*)(g_XTl + (size_t)(b*NN + m0)*CC);
            #pragma unroll
            for (int it = 0; it < 4; it++) {
                int g = it*512 + tid;
                int row = g >> 5, c4 = g & 31;
                int o = row*128 + ((c4 ^ (row & 7)) << 2);
                *(float4*)&sBh[o] = srcH[g];
                *(float4*)&sBl[o] = srcL[g];
            }
            if (tid < 64) sSq[tid] = g_sq[b*NN + m0 + tid];
        }
        __syncthreads();

        float acc[4][4];
        #pragma unroll
        for (int nj = 0; nj < 4; nj++)
            #pragma unroll
            for (int r = 0; r < 4; r++) acc[nj][r] = 0.f;

        // passes: Ah*Bh, Al*Bh, Ah*Bl
        #pragma unroll
        for (int pass = 0; pass < 3; pass++) {
            const uint32_t sA_u = (pass == 1) ? sAl_u : sAh_u;
            const uint32_t sB_u = (pass == 2) ? sBl_u : sBh_u;
            #pragma unroll
            for (int ks = 0; ks < 16; ks++) {
                const int c4a = (ks*2 + ach) ^ (arow & 7);
                uint32_t a0, a1, a2, a3;
                LDSM_X4(a0, a1, a2, a3, sA_u + (uint32_t)(arow*128 + (c4a << 2))*4u);

                const int c4b = (ks*2 + bch);
                uint32_t b00, b01, b10, b11;  // nj0.b0, nj0.b1, nj1.b0, nj1.b1
                LDSM_X4(b00, b01, b10, b11,
                        sB_u + (uint32_t)(brow_lo*128 + ((c4b ^ (brow_lo & 7)) << 2))*4u);
                uint32_t b20, b21, b30, b31;  // nj2, nj3
                const int brow_hi = brow_lo + 16;
                LDSM_X4(b20, b21, b30, b31,
                        sB_u + (uint32_t)(brow_hi*128 + ((c4b ^ (brow_hi & 7)) << 2))*4u);

                MMA_TF32(acc[0][0], acc[0][1], acc[0][2], acc[0][3], a0, a1, a2, a3, b00, b01);
                MMA_TF32(acc[1][0], acc[1][1], acc[1][2], acc[1][3], a0, a1, a2, a3, b10, b11);
                MMA_TF32(acc[2][0], acc[2][1], acc[2][2], acc[2][3], a0, a1, a2, a3, b20, b21);
                MMA_TF32(acc[3][0], acc[3][1], acc[3][2], acc[3][3], a0, a1, a2, a3, b30, b31);
            }
        }

        // epilogue: d = sq[m] - 2*dot; per-thread top-9, rows qr (rl=0) and qr+8 (rl=1)
        #pragma unroll
        for (int nj = 0; nj < 4; nj++)
            #pragma unroll
            for (int r = 0; r < 4; r++) {
                const int rl  = r >> 1;
                const int col = wn + 8*nj + 2*qc + (r & 1);
                float d = sSq[col] - 2.f*acc[nj][r];
                int m = m0 + col;
                if (d < tv[rl][8]) {
                    tv[rl][8] = d; ti[rl][8] = m;
                    #pragma unroll
                    for (int q = 8; q > 0; q--) {
                        if (tv[rl][q] < tv[rl][q-1]) {
                            float fv = tv[rl][q]; tv[rl][q] = tv[rl][q-1]; tv[rl][q-1] = fv;
                            int iv = ti[rl][q];  ti[rl][q] = ti[rl][q-1]; ti[rl][q-1] = iv;
                        }
                    }
                }
            }
    }

    // merge: 8 threads per row x 9 entries = 72 candidates -> 9
    __syncthreads();
    float* mv  = sm;                      // [128][72] values  (36KB)
    int*   mi_ = (int*)(sm + 128*72);     // [128][72] indices (36KB)
    const int slot = (warp & 1)*4 + qc;   // 0..7
    #pragma unroll
    for (int rl = 0; rl < 2; rl++) {
        int row = wm + rl*8 + qr;
        #pragma unroll
        for (int q = 0; q < KK; q++) {
            mv[row*72 + slot*KK + q]  = tv[rl][q];
            mi_[row*72 + slot*KK + q] = ti[rl][q];
        }
    }
    __syncthreads();
    if (tid < 128) {
        const int row = tid;
        float* v = &mv[row*72]; int* ix = &mi_[row*72];
        int base = (b*NN + n0 + row)*KK;
        for (int p = 0; p < KK; p++) {
            float best = FLT_MAX; int bi = 0x7FFFFFFF; int bs = 0;
            for (int s = 0; s < 72; s++) {
                if (v[s] < best || (v[s] == best && ix[s] < bi)) { best = v[s]; bi = ix[s]; bs = s; }
            }
            g_nn[base + p] = bi;
            v[bs] = FLT_MAX;
        }
    }
}

// ------------------------------------------------------------------
// P/Q projection GEMM: PQ[b][n][o'] = sum_c x[b][c][n]*M2T[c][o']
// ------------------------------------------------------------------
#define PTM 128
#define PTN 128
#define PCK 16
__global__ __launch_bounds__(256, 2) void pq_k(const float* __restrict__ x) {
    __shared__ float sX[PCK][PTM];
    __shared__ float sW[PCK][PTN];
    const int tid = threadIdx.x;
    const int b  = blockIdx.z;
    const int n0 = blockIdx.x * PTM;
    const int o0 = blockIdx.y * PTN;
    const float* xb = x + (size_t)b*CC*NN;
    const int tx = tid & 15, ty = tid >> 4;

    float acc[8][8];
    #pragma unroll
    for (int i = 0; i < 8; i++)
        #pragma unroll
        for (int j = 0; j < 8; j++) acc[i][j] = 0.f;

    for (int ck = 0; ck < CC; ck += PCK) {
        __syncthreads();
        {
            int e = tid*4; int cc = e>>7; int r = e&127;
            *(float4*)&sX[cc][r] = *(const float4*)&xb[(size_t)(ck+cc)*NN + n0 + r];
            *(float4*)&sW[cc][r] = *(const float4*)&g_M2T[(ck+cc)*512 + o0 + r];
            e += 1024; cc = e>>7; r = e&127;
            *(float4*)&sX[cc][r] = *(const float4*)&xb[(size_t)(ck+cc)*NN + n0 + r];
            *(float4*)&sW[cc][r] = *(const float4*)&g_M2T[(ck+cc)*512 + o0 + r];
        }
        __syncthreads();
        #pragma unroll
        for (int cc = 0; cc < PCK; cc++) {
            float a[8], w[8];
            *(float4*)a     = *(float4*)&sX[cc][ty*8];
            *(float4*)(a+4) = *(float4*)&sX[cc][ty*8+4];
            *(float4*)w     = *(float4*)&sW[cc][tx*8];
            *(float4*)(w+4) = *(float4*)&sW[cc][tx*8+4];
            #pragma unroll
            for (int i = 0; i < 8; i++)
                #pragma unroll
                for (int j = 0; j < 8; j++)
                    acc[i][j] = fmaf(a[i], w[j], acc[i][j]);
        }
    }
    #pragma unroll
    for (int i = 0; i < 8; i++) {
        float* dst = g_PQ + (size_t)(b*NN + n0 + ty*8 + i)*512 + o0 + tx*8;
        *(float4*)dst     = *(float4*)&acc[i][0];
        *(float4*)(dst+4) = *(float4*)&acc[i][4];
    }
}

// ------------------------------------------------------------------
// gather: h = P[n] + Q[j]; per-row max/min over K; partial BN stats.
// ------------------------------------------------------------------
#define GR 32
__global__ __launch_bounds__(256) void gather_k(const float* __restrict__ gamma) {
    __shared__ int sIdx[GR*KK];
    const int tid = threadIdx.x;
    const int row0 = blockIdx.x * GR;
    for (int i = tid; i < GR*KK; i += 256) sIdx[i] = g_nn[row0*KK + i];
    __syncthreads();
    const float gm = gamma[tid];
    float sum = 0.f, ss = 0.f;
    for (int r = 0; r < GR; r++) {
        int grow = row0 + r;
        int b = grow >> 11;
        float p = g_PQ[(size_t)grow*512 + tid];
        float mx = -FLT_MAX, mn = FLT_MAX;
        #pragma unroll
        for (int k = 0; k < KK; k++) {
            int j = sIdx[r*KK + k];
            float q = g_PQ[(size_t)(b*NN + j)*512 + 256 + tid];
            float h = p + q;
            mx = fmaxf(mx, h); mn = fminf(mn, h);
            sum += h; ss = fmaf(h, h, ss);
        }
        g_Hsel[(size_t)grow*CO + tid] = (gm >= 0.f) ? mx : mn;
    }
    g_part[blockIdx.x*512 + tid]       = sum;
    g_part[blockIdx.x*512 + 256 + tid] = ss;
}

// ------------------------------------------------------------------
// finalize BN affine coefficients
// ------------------------------------------------------------------
__global__ void finalize_k(const float* __restrict__ gamma, const float* __restrict__ beta) {
    int o = threadIdx.x;
    float sum = 0.f, ss = 0.f;
    for (int c = 0; c < 512; c++) {
        sum += g_part[c*512 + o];
        ss  += g_part[c*512 + 256 + o];
    }
    float inv_n = 1.f / (float)((size_t)NROWS*KK);
    float mean = sum * inv_n;
    float var  = ss * inv_n - mean*mean;
    float inv  = rsqrtf(var + 1e-5f);
    float a = inv * gamma[o];
    g_scale[o] = a;
    g_shift[o] = beta[o] - mean * a;
}

// ------------------------------------------------------------------
// output: out[b][o][n] = relu(a[o]*Hsel[b][n][o] + c[o]), 32x32 transpose
// ------------------------------------------------------------------
__global__ void out_k(float* __restrict__ out) {
    __shared__ float t[32][33];
    int b = blockIdx.z, n0 = blockIdx.x*32, o0 = blockIdx.y*32;
    int tx = threadIdx.x, ty = threadIdx.y;
    #pragma unroll
    for (int i = 0; i < 4; i++) {
        int n = n0 + ty + i*8;
        t[ty + i*8][tx] = g_Hsel[(size_t)(b*NN + n)*CO + o0 + tx];
    }
    __syncthreads();
    #pragma unroll
    for (int i = 0; i < 4; i++) {
        int o = o0 + ty + i*8;
        float v = fmaf(g_scale[o], t[tx][ty + i*8], g_shift[o]);
        out[(size_t)(b*CO + o)*NN + n0 + tx] = fmaxf(v, 0.f);
    }
}

// ------------------------------------------------------------------
extern "C" void kernel_launch(void* const* d_in, const int* in_sizes, int n_in,
                              void* d_out, int out_size) {
    const float* x     = (const float*)d_in[0];
    const float* W     = (const float*)d_in[1];
    const float* gamma = (const float*)d_in[2];
    const float* beta  = (const float*)d_in[3];
    float* out = (float*)d_out;

    const int GRAM_SMEM = 48*1024*4;   // 196608 B
    cudaFuncSetAttribute(gram_mma_k, cudaFuncAttributeMaxDynamicSharedMemorySize, GRAM_SMEM);

    prep_k<<<256, 256>>>(W);
    sq_k<<<NROWS/256, 256>>>(x);
    xt_k<<<dim3(NN/32, CC/32, BB), dim3(32, 8)>>>(x);
    gram_mma_k<<<dim3(NN/128, BB), 512, GRAM_SMEM>>>();
    pq_k<<<dim3(NN/PTM, 512/PTN, BB), 256>>>(x);
    gather_k<<<NROWS/GR, 256>>>(gamma);
    finalize_k<<<1, 256>>>(gamma, beta);
    out_k<<<dim3(NN/32, CO/32, BB), dim3(32, 8)>>>(out);
}

// round 7
// speedup vs baseline: 1.9265x; 1.9265x over previous
#include <cuda_runtime.h>
#include <cstdint>
#include <float.h>

#define BB 8
#define NN 2048
#define CC 128
#define KK 9
#define CO 256
#define NROWS (BB*NN)        // 16384

// ---- scratch (device globals: allocation-free contract) ----
__device__ float g_sq[NROWS];
__device__ int   g_nn[NROWS*KK];
__device__ float g_M2T[CC*512];
__device__ float g_PQ[(size_t)NROWS*512];
__device__ float g_Hsel[(size_t)NROWS*CO];
__device__ float g_part[512*512];
__device__ float g_scale[CO];
__device__ float g_shift[CO];
__device__ float g_XTh[(size_t)NROWS*CC];   // x transposed [b][n][c], tf32 hi part
__device__ float g_XTl[(size_t)NROWS*CC];   // tf32 residual

__device__ __forceinline__ float tf32r(float x) {
    uint32_t r;
    asm("cvt.rna.tf32.f32 %0, %1;" : "=r"(r) : "f"(x));
    return __uint_as_float(r);
}

// warp-level tf32 MMA (sm_80+ generic PTX)
#define MMA_TF32(c0,c1,c2,c3, a0,a1,a2,a3, b0,b1)                          \
    asm volatile("mma.sync.aligned.m16n8k8.row.col.f32.tf32.tf32.f32 "     \
        "{%0,%1,%2,%3}, {%4,%5,%6,%7}, {%8,%9}, {%0,%1,%2,%3};"            \
        : "+f"(c0), "+f"(c1), "+f"(c2), "+f"(c3)                           \
        : "r"(a0), "r"(a1), "r"(a2), "r"(a3), "r"(b0), "r"(b1))

// ------------------------------------------------------------------
// prep: M2T = [[W1-W2];[W2]] transposed to [c][o']
// ------------------------------------------------------------------
__global__ void prep_k(const float* __restrict__ W) {
    int i = blockIdx.x*256 + threadIdx.x;
    if (i >= 512*CC) return;
    int c = i >> 9, o = i & 511;
    float v;
    if (o < CO) v = W[o*256 + c] - W[o*256 + 128 + c];
    else        v = W[(o-CO)*256 + 128 + c];
    g_M2T[c*512 + o] = v;
}

// ------------------------------------------------------------------
// sq: per-point squared norm (x layout [b][c][n])
// ------------------------------------------------------------------
__global__ void sq_k(const float* __restrict__ x) {
    int t = blockIdx.x*256 + threadIdx.x;
    int b = t >> 11, n = t & (NN-1);
    const float* xb = x + (size_t)b*CC*NN + n;
    float s = 0.f;
    #pragma unroll 8
    for (int c = 0; c < CC; c++) { float v = xb[(size_t)c*NN]; s = fmaf(v, v, s); }
    g_sq[t] = s;
}

// ------------------------------------------------------------------
// xt: transpose x [b][c][n] -> XTh/XTl [b][n][c] with tf32 hi/lo split
// ------------------------------------------------------------------
__global__ void xt_k(const float* __restrict__ x) {
    __shared__ float t[32][33];
    int b = blockIdx.z, n0 = blockIdx.x*32, c0 = blockIdx.y*32;
    int tx = threadIdx.x, ty = threadIdx.y;   // 32 x 8
    #pragma unroll
    for (int i = 0; i < 4; i++)
        t[ty + i*8][tx] = x[((size_t)(b*CC + c0 + ty + i*8))*NN + n0 + tx];
    __syncthreads();
    #pragma unroll
    for (int i = 0; i < 4; i++) {
        int n = n0 + ty + i*8;
        float v = t[tx][ty + i*8];
        float hi = tf32r(v);
        float lo = tf32r(v - hi);
        size_t idx = ((size_t)(b*NN + n))*CC + c0 + tx;
        g_XTh[idx] = hi;
        g_XTl[idx] = lo;
    }
}

// ------------------------------------------------------------------
// gram_mma v3: tf32 mma.sync Gram (3-pass interleaved) + staged top-9.
// 256 threads = 8 warps (4m x 2n), warp tile 32x32 over 128x64 tiles.
// Epilogue: stage d-tile to smem (overlay B region, pitch 65), remap
// threads 2-per-row -> each thread ONE top-9 list (18 loop-carried regs).
// smem: Ah(128x132) Al(128x132) Bh(64x132) Bl(64x132) = 198KB dynamic.
// ------------------------------------------------------------------
#define PAD 132
#define SDP 65    // staged d-tile pitch: (row*65 + col) % 32 conflict-free scan

__global__ __launch_bounds__(256) void gram_mma_k() {
    extern __shared__ float sm[];
    float* sAh = sm;                    // 128*132
    float* sAl = sm + 128*PAD;          // 128*132
    float* sB  = sm + 256*PAD;          // Bh: 64*132, Bl: 64*132
    float* sBl = sB + 64*PAD;
    float* sD  = sB;                    // overlay: 128*65 <= 64*132*2
    __shared__ float sSq[64];

    const int tid  = threadIdx.x;
    const int warp = tid >> 5, lane = tid & 31;
    const int qr = lane >> 2, qc = lane & 3;
    const int wm = (warp & 3) * 32;    // row base within 128-strip
    const int wn = (warp >> 2) * 32;   // col base within 64-tile
    const int b = blockIdx.y, n0 = blockIdx.x*128;

    // topk scan mapping: 2 threads per row
    const int srow = tid & 127;        // row 0..127
    const int shalf = tid >> 7;        // col half 0/1

    // load A strip (rows n0..n0+127): 128x128 floats, hi+lo
    {
        const float4* srcH = (const float4*)(g_XTh + (size_t)(b*NN + n0)*CC);
        const float4* srcL = (const float4*)(g_XTl + (size_t)(b*NN + n0)*CC);
        #pragma unroll
        for (int it = 0; it < 16; it++) {
            int g = it*256 + tid;
            int row = g >> 5, c4 = (g & 31) * 4;
            *(float4*)&sAh[row*PAD + c4] = srcH[g];
            *(float4*)&sAl[row*PAD + c4] = srcL[g];
        }
    }

    float tv[9]; int ti[9];            // ONE top-9 list per thread
    #pragma unroll
    for (int q = 0; q < KK; q++) { tv[q] = FLT_MAX; ti[q] = 0x7FFFFFFF; }

    for (int mt = 0; mt < NN/64; mt++) {
        const int m0 = mt*64;
        __syncthreads();   // prev scan done; B/sD region reusable
        {
            const float4* srcH = (const float4*)(g_XTh + (size_t)(b*NN + m0)*CC);
            const float4* srcL = (const float4*)(g_XTl + (size_t)(b*NN + m0)*CC);
            #pragma unroll
            for (int it = 0; it < 8; it++) {
                int g = it*256 + tid;
                int row = g >> 5, c4 = (g & 31) * 4;
                *(float4*)&sB [row*PAD + c4] = srcH[g];
                *(float4*)&sBl[row*PAD + c4] = srcL[g];
            }
            if (tid < 64) sSq[tid] = g_sq[b*NN + m0 + tid];
        }
        __syncthreads();

        float acc[2][4][4];
        #pragma unroll
        for (int mi = 0; mi < 2; mi++)
            #pragma unroll
            for (int nj = 0; nj < 4; nj++)
                #pragma unroll
                for (int r = 0; r < 4; r++) acc[mi][nj][r] = 0.f;

        // interleaved 3-pass: load h+l fragments once, 24 MMAs per ks
        #pragma unroll
        for (int ks = 0; ks < 16; ks++) {
            const int k0 = ks*8;
            uint32_t ah[2][4], al[2][4], bh[4][2], bl[4][2];
            #pragma unroll
            for (int mi = 0; mi < 2; mi++) {
                const float* ph = sAh + (wm + 16*mi + qr)*PAD + k0 + qc;
                const float* pl = sAl + (wm + 16*mi + qr)*PAD + k0 + qc;
                ah[mi][0] = __float_as_uint(ph[0]);
                ah[mi][1] = __float_as_uint(ph[8*PAD]);
                ah[mi][2] = __float_as_uint(ph[4]);
                ah[mi][3] = __float_as_uint(ph[8*PAD + 4]);
                al[mi][0] = __float_as_uint(pl[0]);
                al[mi][1] = __float_as_uint(pl[8*PAD]);
                al[mi][2] = __float_as_uint(pl[4]);
                al[mi][3] = __float_as_uint(pl[8*PAD + 4]);
            }
            #pragma unroll
            for (int nj = 0; nj < 4; nj++) {
                const float* ph = sB  + (wn + 8*nj + qr)*PAD + k0 + qc;
                const float* pl = sBl + (wn + 8*nj + qr)*PAD + k0 + qc;
                bh[nj][0] = __float_as_uint(ph[0]);
                bh[nj][1] = __float_as_uint(ph[4]);
                bl[nj][0] = __float_as_uint(pl[0]);
                bl[nj][1] = __float_as_uint(pl[4]);
            }
            #pragma unroll
            for (int mi = 0; mi < 2; mi++)
                #pragma unroll
                for (int nj = 0; nj < 4; nj++) {
                    MMA_TF32(acc[mi][nj][0], acc[mi][nj][1], acc[mi][nj][2], acc[mi][nj][3],
                             ah[mi][0], ah[mi][1], ah[mi][2], ah[mi][3], bh[nj][0], bh[nj][1]);
                    MMA_TF32(acc[mi][nj][0], acc[mi][nj][1], acc[mi][nj][2], acc[mi][nj][3],
                             al[mi][0], al[mi][1], al[mi][2], al[mi][3], bh[nj][0], bh[nj][1]);
                    MMA_TF32(acc[mi][nj][0], acc[mi][nj][1], acc[mi][nj][2], acc[mi][nj][3],
                             ah[mi][0], ah[mi][1], ah[mi][2], ah[mi][3], bl[nj][0], bl[nj][1]);
                }
        }

        // stage d-tile (all warps done reading B -> overlay safe)
        __syncthreads();
        #pragma unroll
        for (int mi = 0; mi < 2; mi++)
            #pragma unroll
            for (int nj = 0; nj < 4; nj++)
                #pragma unroll
                for (int r = 0; r < 4; r++) {
                    const int row = wm + 16*mi + 8*(r >> 1) + qr;
                    const int col = wn + 8*nj + 2*qc + (r & 1);
                    sD[row*SDP + col] = sSq[col] - 2.f*acc[mi][nj][r];
                }
        __syncthreads();

        // top-9 scan: thread (srow, shalf) scans 32 cols, ascending m
        {
            const float* dr = sD + srow*SDP + shalf*32;
            const int mb = m0 + shalf*32;
            #pragma unroll 8
            for (int j = 0; j < 32; j++) {
                float d = dr[j];
                if (d < tv[8]) {
                    tv[8] = d; ti[8] = mb + j;
                    #pragma unroll
                    for (int q = 8; q > 0; q--) {
                        if (tv[q] < tv[q-1]) {
                            float fv = tv[q]; tv[q] = tv[q-1]; tv[q-1] = fv;
                            int iv = ti[q];  ti[q] = ti[q-1]; ti[q-1] = iv;
                        }
                    }
                }
            }
        }
    }

    // merge: 2 threads per row x 9 = 18 candidates -> 9 (overlay A region)
    __syncthreads();
    float* mv  = sm;                   // [128][18] values
    int*   mi_ = (int*)(sm + 128*18);  // [128][18] indices
    #pragma unroll
    for (int q = 0; q < KK; q++) {
        mv[srow*18 + shalf*KK + q]  = tv[q];
        mi_[srow*18 + shalf*KK + q] = ti[q];
    }
    __syncthreads();
    if (tid < 128) {
        const int row = tid;
        float* v = &mv[row*18]; int* ix = &mi_[row*18];
        int base = (b*NN + n0 + row)*KK;
        for (int p = 0; p < KK; p++) {
            float best = FLT_MAX; int bi = 0x7FFFFFFF; int bs = 0;
            #pragma unroll
            for (int s = 0; s < 18; s++) {
                if (v[s] < best || (v[s] == best && ix[s] < bi)) { best = v[s]; bi = ix[s]; bs = s; }
            }
            g_nn[base + p] = bi;
            v[bs] = FLT_MAX;
        }
    }
}

// ------------------------------------------------------------------
// P/Q projection GEMM: PQ[b][n][o'] = sum_c x[b][c][n]*M2T[c][o']
// ------------------------------------------------------------------
#define PTM 128
#define PTN 128
#define PCK 16
__global__ __launch_bounds__(256, 2) void pq_k(const float* __restrict__ x) {
    __shared__ float sX[PCK][PTM];
    __shared__ float sW[PCK][PTN];
    const int tid = threadIdx.x;
    const int b  = blockIdx.z;
    const int n0 = blockIdx.x * PTM;
    const int o0 = blockIdx.y * PTN;
    const float* xb = x + (size_t)b*CC*NN;
    const int tx = tid & 15, ty = tid >> 4;

    float acc[8][8];
    #pragma unroll
    for (int i = 0; i < 8; i++)
        #pragma unroll
        for (int j = 0; j < 8; j++) acc[i][j] = 0.f;

    for (int ck = 0; ck < CC; ck += PCK) {
        __syncthreads();
        {
            int e = tid*4; int cc = e>>7; int r = e&127;
            *(float4*)&sX[cc][r] = *(const float4*)&xb[(size_t)(ck+cc)*NN + n0 + r];
            *(float4*)&sW[cc][r] = *(const float4*)&g_M2T[(ck+cc)*512 + o0 + r];
            e += 1024; cc = e>>7; r = e&127;
            *(float4*)&sX[cc][r] = *(const float4*)&xb[(size_t)(ck+cc)*NN + n0 + r];
            *(float4*)&sW[cc][r] = *(const float4*)&g_M2T[(ck+cc)*512 + o0 + r];
        }
        __syncthreads();
        #pragma unroll
        for (int cc = 0; cc < PCK; cc++) {
            float a[8], w[8];
            *(float4*)a     = *(float4*)&sX[cc][ty*8];
            *(float4*)(a+4) = *(float4*)&sX[cc][ty*8+4];
            *(float4*)w     = *(float4*)&sW[cc][tx*8];
            *(float4*)(w+4) = *(float4*)&sW[cc][tx*8+4];
            #pragma unroll
            for (int i = 0; i < 8; i++)
                #pragma unroll
                for (int j = 0; j < 8; j++)
                    acc[i][j] = fmaf(a[i], w[j], acc[i][j]);
        }
    }
    #pragma unroll
    for (int i = 0; i < 8; i++) {
        float* dst = g_PQ + (size_t)(b*NN + n0 + ty*8 + i)*512 + o0 + tx*8;
        *(float4*)dst     = *(float4*)&acc[i][0];
        *(float4*)(dst+4) = *(float4*)&acc[i][4];
    }
}

// ------------------------------------------------------------------
// gather: h = P[n] + Q[j]; per-row max/min over K; partial BN stats.
// ------------------------------------------------------------------
#define GR 32
__global__ __launch_bounds__(256) void gather_k(const float* __restrict__ gamma) {
    __shared__ int sIdx[GR*KK];
    const int tid = threadIdx.x;
    const int row0 = blockIdx.x * GR;
    for (int i = tid; i < GR*KK; i += 256) sIdx[i] = g_nn[row0*KK + i];
    __syncthreads();
    const float gm = gamma[tid];
    float sum = 0.f, ss = 0.f;
    for (int r = 0; r < GR; r++) {
        int grow = row0 + r;
        int b = grow >> 11;
        float p = g_PQ[(size_t)grow*512 + tid];
        float mx = -FLT_MAX, mn = FLT_MAX;
        #pragma unroll
        for (int k = 0; k < KK; k++) {
            int j = sIdx[r*KK + k];
            float q = g_PQ[(size_t)(b*NN + j)*512 + 256 + tid];
            float h = p + q;
            mx = fmaxf(mx, h); mn = fminf(mn, h);
            sum += h; ss = fmaf(h, h, ss);
        }
        g_Hsel[(size_t)grow*CO + tid] = (gm >= 0.f) ? mx : mn;
    }
    g_part[blockIdx.x*512 + tid]       = sum;
    g_part[blockIdx.x*512 + 256 + tid] = ss;
}

// ------------------------------------------------------------------
// finalize BN affine coefficients
// ------------------------------------------------------------------
__global__ void finalize_k(const float* __restrict__ gamma, const float* __restrict__ beta) {
    int o = threadIdx.x;
    float sum = 0.f, ss = 0.f;
    for (int c = 0; c < 512; c++) {
        sum += g_part[c*512 + o];
        ss  += g_part[c*512 + 256 + o];
    }
    float inv_n = 1.f / (float)((size_t)NROWS*KK);
    float mean = sum * inv_n;
    float var  = ss * inv_n - mean*mean;
    float inv  = rsqrtf(var + 1e-5f);
    float a = inv * gamma[o];
    g_scale[o] = a;
    g_shift[o] = beta[o] - mean * a;
}

// ------------------------------------------------------------------
// output: out[b][o][n] = relu(a[o]*Hsel[b][n][o] + c[o]), 32x32 transpose
// ------------------------------------------------------------------
__global__ void out_k(float* __restrict__ out) {
    __shared__ float t[32][33];
    int b = blockIdx.z, n0 = blockIdx.x*32, o0 = blockIdx.y*32;
    int tx = threadIdx.x, ty = threadIdx.y;
    #pragma unroll
    for (int i = 0; i < 4; i++) {
        int n = n0 + ty + i*8;
        t[ty + i*8][tx] = g_Hsel[(size_t)(b*NN + n)*CO + o0 + tx];
    }
    __syncthreads();
    #pragma unroll
    for (int i = 0; i < 4; i++) {
        int o = o0 + ty + i*8;
        float v = fmaf(g_scale[o], t[tx][ty + i*8], g_shift[o]);
        out[(size_t)(b*CO + o)*NN + n0 + tx] = fmaxf(v, 0.f);
    }
}

// ------------------------------------------------------------------
extern "C" void kernel_launch(void* const* d_in, const int* in_sizes, int n_in,
                              void* d_out, int out_size) {
    const float* x     = (const float*)d_in[0];
    const float* W     = (const float*)d_in[1];
    const float* gamma = (const float*)d_in[2];
    const float* beta  = (const float*)d_in[3];
    float* out = (float*)d_out;

    const int GRAM_SMEM = 384 * PAD * 4;   // 202752 B
    cudaFuncSetAttribute(gram_mma_k, cudaFuncAttributeMaxDynamicSharedMemorySize, GRAM_SMEM);

    prep_k<<<256, 256>>>(W);
    sq_k<<<NROWS/256, 256>>>(x);
    xt_k<<<dim3(NN/32, CC/32, BB), dim3(32, 8)>>>(x);
    gram_mma_k<<<dim3(NN/128, BB), 256, GRAM_SMEM>>>();
    pq_k<<<dim3(NN/PTM, 512/PTN, BB), 256>>>(x);
    gather_k<<<NROWS/GR, 256>>>(gamma);
    finalize_k<<<1, 256>>>(gamma, beta);
    out_k<<<dim3(NN/32, CO/32, BB), dim3(32, 8)>>>(out);
}